// round 7
// baseline (speedup 1.0000x reference)
#include <cuda_runtime.h>
#include <cstdint>

#define LL    320
#define DD    128
#define NBINS 32
#define EPSF  1e-8f

#define Z_ELEMS (LL*LL*DD)     // 13,107,200
#define P_ELEMS (3*LL*LL)      //    307,200
#define NPAIRS  (LL*LL)        // 102,400
// output layout: [z | pxyz | cadistavg], all f32

// ---- cadistavg: 16x16 tiles, upper triangle (symmetric)
#define NT 20                   // 320/16
#define C_BLOCKS 210            // NT*(NT+1)/2
#define CH 16                   // i-chunk depth staged in smem
// ---- balanced grid: stream blocks carry most Z + all P; C blocks take a Z tail share
#define NONC_BLOCKS 750
#define GRID_TOTAL (C_BLOCKS + NONC_BLOCKS)     // 960
#define Z_NONC_PER 127
#define Z_NONC_TOTAL (NONC_BLOCKS * Z_NONC_PER) // 95,250
#define Z_C_PER 35                               // 210*35 >= 102400-95250

__device__ __forceinline__ float fsqrt_approx(float x) {
    float y;
    asm("sqrt.approx.f32 %0, %1;" : "=f"(y) : "f"(x));
    return y;
}

__device__ __forceinline__ float dist3(float4 a, float4 b) {
    float dx = a.x - b.x, dy = a.y - b.y, dz = a.z - b.z;
    return fsqrt_approx(fmaf(dx, dx, fmaf(dy, dy, fmaf(dz, dz, EPSF))));
}

// process pairs [zbeg, zend): one pair per warp per iteration, lane = float4 slot
__device__ __forceinline__ void z_range(int zbeg, int zend, int wid, int lane,
                                        const int* __restrict__ residx,
                                        const int* __restrict__ mask,
                                        const float4* __restrict__ e4,
                                        const float4* __restrict__ pair4,
                                        float4* __restrict__ out4)
{
    int p = zbeg + wid;
    if (p >= zend) return;
    int i = p / LL;
    int j = p - i * LL;
    for (; p < zend; p += 8) {
        int m   = mask[i] & mask[j];
        int dif = residx[j] - residx[i];
        dif = min(max(dif, -NBINS), NBINS) + (NBINS + 1);
        const int idx = m ? dif : 0;

        float4 ev = e4[idx * (DD / 4) + lane];
        float4 pv = pair4[(size_t)p * (DD / 4) + lane];
        out4[(size_t)p * (DD / 4) + lane] =
            make_float4(pv.x + ev.x, pv.y + ev.y, pv.z + ev.z, pv.w + ev.w);

        j += 8;
        if (j >= LL) { j -= LL; i++; }   // stride 8 divides 320: exact wrap
    }
}

__global__ void spired_fused(const int* __restrict__ residx,
                             const int* __restrict__ mask,   // bool delivered as int32
                             const float* __restrict__ emb,
                             const float4* __restrict__ pair4,
                             const float* __restrict__ predxyz,
                             const float* __restrict__ maskdiag,
                             float* __restrict__ out)
{
    const int blk  = blockIdx.x;
    const int tid  = threadIdx.x;
    const int wid  = tid >> 5;
    const int lane = tid & 31;
    const float4* e4 = (const float4*)emb;

    if (blk < C_BLOCKS) {
        // ---- cadistavg 16x16 tile (upper triangle + mirror), then Z tail share
        __shared__ float4 sK[CH][16];
        __shared__ float4 sJ[CH][16];

        int a = 0, t = blk;
        while (t >= NT - a) { t -= NT - a; a++; }
        const int b2 = a + t;
        const int jt = a * 16;
        const int kt = b2 * 16;

        const int tx = tid & 15;
        const int ty = tid >> 4;

        float acc0 = 0.f, acc1 = 0.f, acc2 = 0.f, acc3 = 0.f;

        for (int i0 = 0; i0 < LL; i0 += CH) {
            const int gi = i0 + ty;
            {
                int col = kt + tx;
                float md = maskdiag[gi * LL + col];
                sK[ty][tx] = make_float4(
                    predxyz[0 * LL * LL + gi * LL + col] * md,
                    predxyz[1 * LL * LL + gi * LL + col] * md,
                    predxyz[2 * LL * LL + gi * LL + col] * md, 0.f);
                col = jt + tx;
                md = maskdiag[gi * LL + col];
                sJ[ty][tx] = make_float4(
                    predxyz[0 * LL * LL + gi * LL + col] * md,
                    predxyz[1 * LL * LL + gi * LL + col] * md,
                    predxyz[2 * LL * LL + gi * LL + col] * md, 0.f);
            }
            __syncthreads();
            #pragma unroll
            for (int ii = 0; ii < CH; ii += 4) {
                acc0 += dist3(sK[ii + 0][tx], sJ[ii + 0][ty]);
                acc1 += dist3(sK[ii + 1][tx], sJ[ii + 1][ty]);
                acc2 += dist3(sK[ii + 2][tx], sJ[ii + 2][ty]);
                acc3 += dist3(sK[ii + 3][tx], sJ[ii + 3][ty]);
            }
            __syncthreads();
        }

        float* cd = out + Z_ELEMS + P_ELEMS;
        const float v = (acc0 + acc1 + acc2 + acc3) * (1.0f / LL);
        cd[(jt + ty) * LL + (kt + tx)] = v;
        if (a != b2)
            cd[(kt + tx) * LL + (jt + ty)] = v;

        // Z tail share
        const int zbeg = Z_NONC_TOTAL + blk * Z_C_PER;
        const int zend = min(zbeg + Z_C_PER, NPAIRS);
        z_range(zbeg, zend, wid, lane, residx, mask, e4, pair4, (float4*)out);

    } else {
        // ---- stream block: Z slice then P slice
        const int nb   = blk - C_BLOCKS;
        const int zbeg = nb * Z_NONC_PER;
        z_range(zbeg, zbeg + Z_NONC_PER, wid, lane, residx, mask, e4, pair4,
                (float4*)out);

        // pxyz = predxyz * maskdiag (float4-wide), 76800 elems over 750 blocks
        const int e = nb * 256 + tid;
        if (e < P_ELEMS / 4) {
            const float4* pr4 = (const float4*)predxyz;
            const float4* md4 = (const float4*)maskdiag;
            float4 pv = pr4[e];
            float4 mv = md4[e % (LL * LL / 4)];
            ((float4*)(out + Z_ELEMS))[e] =
                make_float4(pv.x * mv.x, pv.y * mv.y, pv.z * mv.z, pv.w * mv.w);
        }
    }
}

extern "C" void kernel_launch(void* const* d_in, const int* in_sizes, int n_in,
                              void* d_out, int out_size) {
    const int*    residx   = (const int*)d_in[0];
    const int*    mask     = (const int*)d_in[1];
    const float*  emb      = (const float*)d_in[2];
    const float4* pair4    = (const float4*)d_in[3];
    const float*  predxyz  = (const float*)d_in[4];
    const float*  maskdiag = (const float*)d_in[5];
    float*        out      = (float*)d_out;

    spired_fused<<<GRID_TOTAL, 256>>>(residx, mask, emb, pair4, predxyz,
                                      maskdiag, out);
}